// round 5
// baseline (speedup 1.0000x reference)
#include <cuda_runtime.h>
#include <cuda_bf16.h>
#include <cstdint>

// Problem dims (fixed)
#define BATCH 2
#define SEQ   2048
#define DIM   4096
#define NH    32
#define NKV   8
#define HD    128
#define NREP  4
#define MTOT  (BATCH*SEQ)          // 4096
#define KVD   (NKV*HD)             // 1024

// ---------------- scratch (static device globals; no allocation) ----------
__device__ float g_xq[(size_t)MTOT * DIM];
__device__ float g_xk[(size_t)MTOT * KVD];
__device__ float g_xv[(size_t)MTOT * KVD];
__device__ float g_attn[(size_t)MTOT * DIM];

__device__ __nv_bfloat16 g_xh[(size_t)MTOT * DIM];
__device__ __nv_bfloat16 g_xl[(size_t)MTOT * DIM];
__device__ __nv_bfloat16 g_ah[(size_t)MTOT * DIM];
__device__ __nv_bfloat16 g_al[(size_t)MTOT * DIM];
__device__ __nv_bfloat16 g_wqh[(size_t)DIM * DIM];   // transposed [N][K]
__device__ __nv_bfloat16 g_wql[(size_t)DIM * DIM];
__device__ __nv_bfloat16 g_wkh[(size_t)KVD * DIM];
__device__ __nv_bfloat16 g_wkl[(size_t)KVD * DIM];
__device__ __nv_bfloat16 g_wvh[(size_t)KVD * DIM];
__device__ __nv_bfloat16 g_wvl[(size_t)KVD * DIM];
__device__ __nv_bfloat16 g_woh[(size_t)DIM * DIM];
__device__ __nv_bfloat16 g_wol[(size_t)DIM * DIM];

// ---------------- common helpers -----------------------------------------
__device__ __forceinline__ uint32_t smem_u32(const void* p) {
    uint32_t a;
    asm("{ .reg .u64 t; cvta.to.shared.u64 t, %1; cvt.u32.u64 %0, t; }"
        : "=r"(a) : "l"(p));
    return a;
}
__device__ __forceinline__ void cp16(uint32_t dst, const void* src) {
    asm volatile("cp.async.cg.shared.global [%0], [%1], 16;"
                 :: "r"(dst), "l"(src) : "memory");
}
#define CP_COMMIT() asm volatile("cp.async.commit_group;" ::: "memory")
#define CP_WAIT2()  asm volatile("cp.async.wait_group 2;" ::: "memory")

__device__ __forceinline__ void mma_bf16(float* d, uint32_t a0, uint32_t a1,
                                         uint32_t a2, uint32_t a3,
                                         uint32_t b0, uint32_t b1) {
    asm volatile(
        "mma.sync.aligned.m16n8k16.row.col.f32.bf16.bf16.f32 "
        "{%0,%1,%2,%3},{%4,%5,%6,%7},{%8,%9},{%0,%1,%2,%3};"
        : "+f"(d[0]), "+f"(d[1]), "+f"(d[2]), "+f"(d[3])
        : "r"(a0), "r"(a1), "r"(a2), "r"(a3), "r"(b0), "r"(b1));
}
__device__ __forceinline__ void ldm_x4(uint32_t& r0, uint32_t& r1,
                                       uint32_t& r2, uint32_t& r3, uint32_t a) {
    asm volatile("ldmatrix.sync.aligned.m8n8.x4.shared.b16 {%0,%1,%2,%3}, [%4];"
                 : "=r"(r0), "=r"(r1), "=r"(r2), "=r"(r3) : "r"(a));
}
__device__ __forceinline__ uint32_t packbf(__nv_bfloat16 lo, __nv_bfloat16 hi) {
    __nv_bfloat162 p(lo, hi);
    return *(uint32_t*)&p;
}
__device__ __forceinline__ uint32_t pack_f2(float lo, float hi) {
    return packbf(__float2bfloat16_rn(lo), __float2bfloat16_rn(hi));
}
__device__ __forceinline__ void split2(float v, __nv_bfloat16& h, __nv_bfloat16& l) {
    h = __float2bfloat16_rn(v);
    l = __float2bfloat16_rn(v - __bfloat162float(h));
}
__device__ __forceinline__ uint32_t ld32s(const __nv_bfloat16* p) {
    return *(const uint32_t*)p;
}

// ================= bf16-split tensor-core GEMM ===========================
// C[M,N] = (Ah+Al)[M,K] @ (Bh+Bl)^T  with B stored transposed [N][K].
// 3-term: AhBh + AhBl + AlBh. Block 128x128, BK=32 halves, 3-stage cp.async.
// 8 warps: 2(M) x 4(N); warp tile 64m x 32n.
#define BPH 40                         // halves per smem row (80 B)
#define TILE_HB (128 * BPH * 2)        // 10240 B per tile
#define STAGE_HB (4 * TILE_HB)         // 40960 B  (Ah, Al, Bh, Bl)
#define BG_SMEM (3 * STAGE_HB)         // 122880 B

__global__ __launch_bounds__(256, 1)
void bf_gemm(const __nv_bfloat16* __restrict__ Ah,
             const __nv_bfloat16* __restrict__ Al,
             const __nv_bfloat16* __restrict__ Bh,
             const __nv_bfloat16* __restrict__ Bl,
             float* __restrict__ C, int M, int N, int K)
{
    extern __shared__ char smem[];
    const uint32_t sb = smem_u32(smem);
    const int tid  = threadIdx.x;
    const int wid  = tid >> 5;
    const int lane = tid & 31;
    const int warpM = wid >> 2;        // 0..1
    const int warpN = wid & 3;         // 0..3
    const int g = lane >> 2;
    const int c = lane & 3;

    const int bm = blockIdx.y * 128;
    const int bn = blockIdx.x * 128;

    float acc[4][4][4];
#pragma unroll
    for (int i = 0; i < 4; i++)
#pragma unroll
        for (int j = 0; j < 4; j++)
#pragma unroll
            for (int r = 0; r < 4; r++) acc[i][j][r] = 0.f;

    const int nt = K / 32;

    // per-thread cp.async: 2 chunks x 4 tiles. lin = v*256+tid:
    // row = lin>>2 (0..127), cc = lin&3 (16B chunk = 8 halves)
    auto issue = [&](int t, int buf) {
        const uint32_t base = sb + buf * STAGE_HB;
#pragma unroll
        for (int v = 0; v < 2; v++) {
            int lin = v * 256 + tid;
            int row = lin >> 2, cc = lin & 3;
            uint32_t dst = base + row * (BPH * 2) + cc * 16;
            size_t goff = (size_t)row * K + t * 32 + cc * 8;
            cp16(dst,               Ah + (size_t)bm * K + goff);
            cp16(dst + TILE_HB,     Al + (size_t)bm * K + goff);
            cp16(dst + 2 * TILE_HB, Bh + (size_t)bn * K + goff);
            cp16(dst + 3 * TILE_HB, Bl + (size_t)bn * K + goff);
        }
        CP_COMMIT();
    };

    issue(0, 0);
    issue(1, 1);

    const uint32_t lrow = (lane & 15);
    const uint32_t lcol = (lane >> 4) * 8;

    for (int t = 0; t < nt; t++) {
        if (t + 2 < nt) issue(t + 2, (t + 2) % 3);
        CP_WAIT2();
        __syncthreads();

        const uint32_t base = sb + (t % 3) * STAGE_HB;

#pragma unroll
        for (int ks = 0; ks < 2; ks++) {
            const uint32_t kofs = (ks * 16 + lcol) * 2;
            uint32_t ah[4][4], al4[4][4], bh[4][2], bl4[4][2];
#pragma unroll
            for (int mi = 0; mi < 4; mi++) {
                uint32_t addr = base + (warpM * 64 + mi * 16 + lrow) * (BPH * 2) + kofs;
                ldm_x4(ah[mi][0], ah[mi][1], ah[mi][2], ah[mi][3], addr);
                ldm_x4(al4[mi][0], al4[mi][1], al4[mi][2], al4[mi][3], addr + TILE_HB);
            }
#pragma unroll
            for (int ni = 0; ni < 2; ni++) {
                uint32_t addr = base + 2 * TILE_HB +
                                (warpN * 32 + ni * 16 + lrow) * (BPH * 2) + kofs;
                uint32_t r0, r1, r2, r3;
                ldm_x4(r0, r1, r2, r3, addr);
                bh[ni * 2][0] = r0; bh[ni * 2][1] = r2;
                bh[ni * 2 + 1][0] = r1; bh[ni * 2 + 1][1] = r3;
                ldm_x4(r0, r1, r2, r3, addr + TILE_HB);
                bl4[ni * 2][0] = r0; bl4[ni * 2][1] = r2;
                bl4[ni * 2 + 1][0] = r1; bl4[ni * 2 + 1][1] = r3;
            }
#pragma unroll
            for (int mi = 0; mi < 4; mi++)
#pragma unroll
                for (int j = 0; j < 4; j++) {
                    mma_bf16(acc[mi][j], ah[mi][0], ah[mi][1], ah[mi][2], ah[mi][3],
                             bh[j][0], bh[j][1]);
                    mma_bf16(acc[mi][j], ah[mi][0], ah[mi][1], ah[mi][2], ah[mi][3],
                             bl4[j][0], bl4[j][1]);
                    mma_bf16(acc[mi][j], al4[mi][0], al4[mi][1], al4[mi][2], al4[mi][3],
                             bh[j][0], bh[j][1]);
                }
        }
        __syncthreads();
    }

    // epilogue
#pragma unroll
    for (int mi = 0; mi < 4; mi++) {
        int row = bm + warpM * 64 + mi * 16 + g;
#pragma unroll
        for (int j = 0; j < 4; j++) {
            int col = bn + warpN * 32 + j * 8 + 2 * c;
            float2 v0, v1;
            v0.x = acc[mi][j][0]; v0.y = acc[mi][j][1];
            v1.x = acc[mi][j][2]; v1.y = acc[mi][j][3];
            *(float2*)(C + (size_t)row * N + col)       = v0;
            *(float2*)(C + (size_t)(row + 8) * N + col) = v1;
        }
    }
}

// ============ conversion kernels =========================================
__global__ __launch_bounds__(256)
void split_kernel(const float4* __restrict__ x, __nv_bfloat16* __restrict__ hi,
                  __nv_bfloat16* __restrict__ lo)
{
    const int i = blockIdx.x * 256 + threadIdx.x;
    float4 v = x[i];
    __nv_bfloat16 h0, h1, h2, h3, l0, l1, l2, l3;
    split2(v.x, h0, l0); split2(v.y, h1, l1);
    split2(v.z, h2, l2); split2(v.w, h3, l3);
    uint2 hv, lv;
    hv.x = packbf(h0, h1); hv.y = packbf(h2, h3);
    lv.x = packbf(l0, l1); lv.y = packbf(l2, l3);
    *(uint2*)(hi + (size_t)i * 4) = hv;
    *(uint2*)(lo + (size_t)i * 4) = lv;
}

// transpose + split: w[K,N] fp32 -> [N][K] bf16 hi/lo
__global__ __launch_bounds__(256)
void transpose_split(const float* __restrict__ w, __nv_bfloat16* __restrict__ th,
                     __nv_bfloat16* __restrict__ tl, int K, int N)
{
    __shared__ float t[32][33];
    const int k0 = blockIdx.y * 32, n0 = blockIdx.x * 32;
    const int r = threadIdx.x >> 5, cc = threadIdx.x & 31;
#pragma unroll
    for (int i = 0; i < 4; i++)
        t[r + i * 8][cc] = w[(size_t)(k0 + r + i * 8) * N + n0 + cc];
    __syncthreads();
#pragma unroll
    for (int i = 0; i < 4; i++) {
        float v = t[cc][r + i * 8];
        __nv_bfloat16 h, l;
        split2(v, h, l);
        size_t o = (size_t)(n0 + r + i * 8) * K + k0 + cc;
        th[o] = h;
        tl[o] = l;
    }
}

// ---------------- RoPE (in place) ----------------------------------------
__global__ __launch_bounds__(256)
void rope_kernel(float2* __restrict__ x, const float* __restrict__ cs,
                 const float* __restrict__ sn, int heads)
{
    const int idx = blockIdx.x * blockDim.x + threadIdx.x;
    const int pair = idx & 63;
    const int row  = idx >> 6;
    const int s    = (row / heads) & (SEQ - 1);
    const float c  = cs[s * 64 + pair];
    const float si = sn[s * 64 + pair];
    float2 v = x[idx];
    float2 o;
    o.x = v.x * c - v.y * si;
    o.y = v.x * si + v.y * c;
    x[idx] = o;
}

// ============ bf16-split tensor-core flash attention =====================
#define QPITCH 136
#define KPITCH 136
#define VPITCH 68
#define OFF_QH 0
#define OFF_QL (OFF_QH + 128 * QPITCH * 2)
#define OFF_KH (OFF_QL + 128 * QPITCH * 2)
#define OFF_KL (OFF_KH + 64 * KPITCH * 2)
#define OFF_VH (OFF_KL + 64 * KPITCH * 2)
#define OFF_VL (OFF_VH + 128 * VPITCH * 2)
#define ATT_SMEM (OFF_VL + 128 * VPITCH * 2)     // 139264

__global__ __launch_bounds__(256, 1)
void attention_mma(const float* __restrict__ q, const float* __restrict__ k,
                   const float* __restrict__ v, float* __restrict__ o)
{
    extern __shared__ char sm[];
    __nv_bfloat16* Qh  = (__nv_bfloat16*)(sm + OFF_QH);
    __nv_bfloat16* Ql  = (__nv_bfloat16*)(sm + OFF_QL);
    __nv_bfloat16* Kh  = (__nv_bfloat16*)(sm + OFF_KH);
    __nv_bfloat16* Kl  = (__nv_bfloat16*)(sm + OFF_KL);
    __nv_bfloat16* Vth = (__nv_bfloat16*)(sm + OFF_VH);
    __nv_bfloat16* Vtl = (__nv_bfloat16*)(sm + OFF_VL);

    const int tid  = threadIdx.x;
    const int wid  = tid >> 5;
    const int lane = tid & 31;
    const int g = lane >> 2;
    const int c = lane & 3;
    const int b  = blockIdx.z;
    const int h  = blockIdx.y;
    const int kvh = h >> 2;
    const int q0 = blockIdx.x * 128;

    const float inv_sqrt = 0.08838834764831845f;

    {
        const float* qb = q + ((size_t)(b * SEQ + q0) * NH + h) * HD;
#pragma unroll
        for (int i = 0; i < 16; i++) {
            int lin = i * 256 + tid;
            int r = lin >> 5, d4 = (lin & 31) << 2;
            float4 qv = *(const float4*)(qb + (size_t)r * (NH * HD) + d4);
            qv.x *= inv_sqrt; qv.y *= inv_sqrt; qv.z *= inv_sqrt; qv.w *= inv_sqrt;
            __nv_bfloat16 h0, h1, h2, h3, l0, l1, l2, l3;
            split2(qv.x, h0, l0); split2(qv.y, h1, l1);
            split2(qv.z, h2, l2); split2(qv.w, h3, l3);
            uint2 hv, lv;
            hv.x = packbf(h0, h1); hv.y = packbf(h2, h3);
            lv.x = packbf(l0, l1); lv.y = packbf(l2, l3);
            *(uint2*)(Qh + r * QPITCH + d4) = hv;
            *(uint2*)(Ql + r * QPITCH + d4) = lv;
        }
    }

    float m0 = -1e30f, m1 = -1e30f, l0s = 0.f, l1s = 0.f;
    float oacc[16][4];
#pragma unroll
    for (int j = 0; j < 16; j++)
#pragma unroll
        for (int r = 0; r < 4; r++) oacc[j][r] = 0.f;

    const float* kb0 = k + ((size_t)(b * SEQ) * NKV + kvh) * HD;
    const float* vb0 = v + ((size_t)(b * SEQ) * NKV + kvh) * HD;

    for (int kt = 0; kt < SEQ / 64; kt++) {
        __syncthreads();
        {
            const float* kb = kb0 + (size_t)(kt * 64) * KVD;
#pragma unroll
            for (int i = 0; i < 8; i++) {
                int lin = i * 256 + tid;
                int r = lin >> 5, d4 = (lin & 31) << 2;
                float4 kv = *(const float4*)(kb + (size_t)r * KVD + d4);
                __nv_bfloat16 h0, h1, h2, h3, lo0, lo1, lo2, lo3;
                split2(kv.x, h0, lo0); split2(kv.y, h1, lo1);
                split2(kv.z, h2, lo2); split2(kv.w, h3, lo3);
                uint2 hv, lv;
                hv.x = packbf(h0, h1); hv.y = packbf(h2, h3);
                lv.x = packbf(lo0, lo1); lv.y = packbf(lo2, lo3);
                *(uint2*)(Kh + r * KPITCH + d4) = hv;
                *(uint2*)(Kl + r * KPITCH + d4) = lv;
            }
        }
        {
            const float* vb = vb0 + (size_t)(kt * 64) * KVD;
            const int d  = tid & 127;
            const int rg = (tid >> 7) << 2;
#pragma unroll
            for (int it = 0; it < 8; it++) {
                int r0 = rg + it * 8;
                __nv_bfloat16 vh[4], vl[4];
#pragma unroll
                for (int i = 0; i < 4; i++) {
                    float val = vb[(size_t)(r0 + i) * KVD + d];
                    split2(val, vh[i], vl[i]);
                }
                uint2 hv, lv;
                hv.x = packbf(vh[0], vh[1]); hv.y = packbf(vh[2], vh[3]);
                lv.x = packbf(vl[0], vl[1]); lv.y = packbf(vl[2], vl[3]);
                *(uint2*)(Vth + d * VPITCH + r0) = hv;
                *(uint2*)(Vtl + d * VPITCH + r0) = lv;
            }
        }
        __syncthreads();

        float s[8][4];
#pragma unroll
        for (int j = 0; j < 8; j++)
#pragma unroll
            for (int r = 0; r < 4; r++) s[j][r] = 0.f;

#pragma unroll
        for (int kk = 0; kk < 8; kk++) {
            const int dofs = kk * 16 + 2 * c;
            const __nv_bfloat16* qhp = Qh + (wid * 16 + g) * QPITCH + dofs;
            const __nv_bfloat16* qlp = Ql + (wid * 16 + g) * QPITCH + dofs;
            uint32_t ah0 = ld32s(qhp),     ah1 = ld32s(qhp + 8 * QPITCH);
            uint32_t ah2 = ld32s(qhp + 8), ah3 = ld32s(qhp + 8 * QPITCH + 8);
            uint32_t al0 = ld32s(qlp),     al1 = ld32s(qlp + 8 * QPITCH);
            uint32_t al2 = ld32s(qlp + 8), al3 = ld32s(qlp + 8 * QPITCH + 8);
#pragma unroll
            for (int j = 0; j < 8; j++) {
                const __nv_bfloat16* khp = Kh + (8 * j + g) * KPITCH + dofs;
                const __nv_bfloat16* klp = Kl + (8 * j + g) * KPITCH + dofs;
                uint32_t bh0 = ld32s(khp), bh1 = ld32s(khp + 8);
                uint32_t bl0 = ld32s(klp), bl1 = ld32s(klp + 8);
                mma_bf16(s[j], ah0, ah1, ah2, ah3, bh0, bh1);
                mma_bf16(s[j], ah0, ah1, ah2, ah3, bl0, bl1);
                mma_bf16(s[j], al0, al1, al2, al3, bh0, bh1);
            }
        }

        float mx0 = s[0][0], mx1 = s[0][2];
#pragma unroll
        for (int j = 0; j < 8; j++) {
            mx0 = fmaxf(mx0, fmaxf(s[j][0], s[j][1]));
            mx1 = fmaxf(mx1, fmaxf(s[j][2], s[j][3]));
        }
        mx0 = fmaxf(mx0, __shfl_xor_sync(0xffffffffu, mx0, 1));
        mx0 = fmaxf(mx0, __shfl_xor_sync(0xffffffffu, mx0, 2));
        mx1 = fmaxf(mx1, __shfl_xor_sync(0xffffffffu, mx1, 1));
        mx1 = fmaxf(mx1, __shfl_xor_sync(0xffffffffu, mx1, 2));
        float mn0 = fmaxf(m0, mx0), mn1 = fmaxf(m1, mx1);
        float f0 = __expf(m0 - mn0), f1 = __expf(m1 - mn1);
        float rs0 = 0.f, rs1 = 0.f;
#pragma unroll
        for (int j = 0; j < 8; j++) {
            s[j][0] = __expf(s[j][0] - mn0);
            s[j][1] = __expf(s[j][1] - mn0);
            s[j][2] = __expf(s[j][2] - mn1);
            s[j][3] = __expf(s[j][3] - mn1);
            rs0 += s[j][0] + s[j][1];
            rs1 += s[j][2] + s[j][3];
        }
        rs0 += __shfl_xor_sync(0xffffffffu, rs0, 1);
        rs0 += __shfl_xor_sync(0xffffffffu, rs0, 2);
        rs1 += __shfl_xor_sync(0xffffffffu, rs1, 1);
        rs1 += __shfl_xor_sync(0xffffffffu, rs1, 2);
        l0s = l0s * f0 + rs0;
        l1s = l1s * f1 + rs1;
        m0 = mn0; m1 = mn1;
#pragma unroll
        for (int j = 0; j < 16; j++) {
            oacc[j][0] *= f0; oacc[j][1] *= f0;
            oacc[j][2] *= f1; oacc[j][3] *= f1;
        }

#pragma unroll
        for (int kk = 0; kk < 4; kk++) {
            const int j0 = 2 * kk, j1 = 2 * kk + 1;
            uint32_t ph0 = pack_f2(s[j0][0], s[j0][1]);
            uint32_t ph1 = pack_f2(s[j0][2], s[j0][3]);
            uint32_t ph2 = pack_f2(s[j1][0], s[j1][1]);
            uint32_t ph3 = pack_f2(s[j1][2], s[j1][3]);
            __nv_bfloat162 h0 = *(__nv_bfloat162*)&ph0;
            __nv_bfloat162 h1 = *(__nv_bfloat162*)&ph1;
            __nv_bfloat162 h2 = *(__nv_bfloat162*)&ph2;
            __nv_bfloat162 h3 = *(__nv_bfloat162*)&ph3;
            uint32_t pl0 = pack_f2(s[j0][0] - __bfloat162float(h0.x),
                                   s[j0][1] - __bfloat162float(h0.y));
            uint32_t pl1 = pack_f2(s[j0][2] - __bfloat162float(h1.x),
                                   s[j0][3] - __bfloat162float(h1.y));
            uint32_t pl2 = pack_f2(s[j1][0] - __bfloat162float(h2.x),
                                   s[j1][1] - __bfloat162float(h2.y));
            uint32_t pl3 = pack_f2(s[j1][2] - __bfloat162float(h3.x),
                                   s[j1][3] - __bfloat162float(h3.y));
            const int kofs = kk * 16 + 2 * c;
#pragma unroll
            for (int j = 0; j < 16; j++) {
                const __nv_bfloat16* vhp = Vth + (8 * j + g) * VPITCH + kofs;
                const __nv_bfloat16* vlp = Vtl + (8 * j + g) * VPITCH + kofs;
                uint32_t bh0 = ld32s(vhp), bh1 = ld32s(vhp + 8);
                uint32_t bl0 = ld32s(vlp), bl1 = ld32s(vlp + 8);
                mma_bf16(oacc[j], ph0, ph1, ph2, ph3, bh0, bh1);
                mma_bf16(oacc[j], ph0, ph1, ph2, ph3, bl0, bl1);
                mma_bf16(oacc[j], pl0, pl1, pl2, pl3, bh0, bh1);
            }
        }
    }

    const float inv0 = 1.f / l0s, inv1 = 1.f / l1s;
    float* ob  = o + ((size_t)(b * SEQ + q0 + wid * 16 + g) * NH + h) * HD;
    float* ob8 = ob + (size_t)8 * NH * HD;
#pragma unroll
    for (int j = 0; j < 16; j++) {
        int col = j * 8 + 2 * c;
        float2 v0, v1;
        v0.x = oacc[j][0] * inv0; v0.y = oacc[j][1] * inv0;
        v1.x = oacc[j][2] * inv1; v1.y = oacc[j][3] * inv1;
        *(float2*)(ob + col)  = v0;
        *(float2*)(ob8 + col) = v1;
    }
}

// ---------------- launch -------------------------------------------------
extern "C" void kernel_launch(void* const* d_in, const int* in_sizes, int n_in,
                              void* d_out, int out_size)
{
    (void)in_sizes; (void)n_in; (void)out_size;
    const float* x  = (const float*)d_in[0];
    const float* wq = (const float*)d_in[1];
    const float* wk = (const float*)d_in[2];
    const float* wv = (const float*)d_in[3];
    const float* wo = (const float*)d_in[4];
    const float* fc = (const float*)d_in[5];
    const float* fs = (const float*)d_in[6];
    float* out = (float*)d_out;

    float *xq, *xk, *xv, *attn;
    __nv_bfloat16 *xh, *xl, *ah, *al;
    __nv_bfloat16 *wqh, *wql, *wkh, *wkl, *wvh, *wvl, *woh, *wol;
    cudaGetSymbolAddress((void**)&xq,   g_xq);
    cudaGetSymbolAddress((void**)&xk,   g_xk);
    cudaGetSymbolAddress((void**)&xv,   g_xv);
    cudaGetSymbolAddress((void**)&attn, g_attn);
    cudaGetSymbolAddress((void**)&xh,  g_xh);
    cudaGetSymbolAddress((void**)&xl,  g_xl);
    cudaGetSymbolAddress((void**)&ah,  g_ah);
    cudaGetSymbolAddress((void**)&al,  g_al);
    cudaGetSymbolAddress((void**)&wqh, g_wqh);
    cudaGetSymbolAddress((void**)&wql, g_wql);
    cudaGetSymbolAddress((void**)&wkh, g_wkh);
    cudaGetSymbolAddress((void**)&wkl, g_wkl);
    cudaGetSymbolAddress((void**)&wvh, g_wvh);
    cudaGetSymbolAddress((void**)&wvl, g_wvl);
    cudaGetSymbolAddress((void**)&woh, g_woh);
    cudaGetSymbolAddress((void**)&wol, g_wol);

    cudaFuncSetAttribute(bf_gemm,
                         cudaFuncAttributeMaxDynamicSharedMemorySize, BG_SMEM);
    cudaFuncSetAttribute(attention_mma,
                         cudaFuncAttributeMaxDynamicSharedMemorySize, ATT_SMEM);

    // conversions
    split_kernel<<<(MTOT * DIM / 4) / 256, 256>>>((const float4*)x, xh, xl);
    transpose_split<<<dim3(DIM / 32, DIM / 32), 256>>>(wq, wqh, wql, DIM, DIM);
    transpose_split<<<dim3(KVD / 32, DIM / 32), 256>>>(wk, wkh, wkl, DIM, KVD);
    transpose_split<<<dim3(KVD / 32, DIM / 32), 256>>>(wv, wvh, wvl, DIM, KVD);
    transpose_split<<<dim3(DIM / 32, DIM / 32), 256>>>(wo, woh, wol, DIM, DIM);

    // QKV projections (bf16 split, 3-term)
    bf_gemm<<<dim3(DIM / 128, MTOT / 128), 256, BG_SMEM>>>(xh, xl, wqh, wql, xq, MTOT, DIM, DIM);
    bf_gemm<<<dim3(KVD / 128, MTOT / 128), 256, BG_SMEM>>>(xh, xl, wkh, wkl, xk, MTOT, KVD, DIM);
    bf_gemm<<<dim3(KVD / 128, MTOT / 128), 256, BG_SMEM>>>(xh, xl, wvh, wvl, xv, MTOT, KVD, DIM);

    // RoPE
    rope_kernel<<<(MTOT * NH * (HD / 2)) / 256, 256>>>((float2*)xq, fc, fs, NH);
    rope_kernel<<<(MTOT * NKV * (HD / 2)) / 256, 256>>>((float2*)xk, fc, fs, NKV);

    // attention (bf16-split mma)
    attention_mma<<<dim3(SEQ / 128, NH, BATCH), 256, ATT_SMEM>>>(xq, xk, xv, attn);

    // output projection
    split_kernel<<<(MTOT * DIM / 4) / 256, 256>>>((const float4*)attn, ah, al);
    bf_gemm<<<dim3(DIM / 128, MTOT / 128), 256, BG_SMEM>>>(ah, al, woh, wol, out, MTOT, DIM, DIM);
}

// round 6
// speedup vs baseline: 1.4221x; 1.4221x over previous
#include <cuda_runtime.h>
#include <cuda_bf16.h>
#include <cstdint>

// Problem dims (fixed)
#define BATCH 2
#define SEQ   2048
#define DIM   4096
#define NH    32
#define NKV   8
#define HD    128
#define NREP  4
#define MTOT  (BATCH*SEQ)          // 4096
#define KVD   (NKV*HD)             // 1024

// ---------------- scratch (static device globals; no allocation) ----------
__device__ float g_xq[(size_t)MTOT * DIM];
__device__ float g_xk[(size_t)MTOT * KVD];
__device__ float g_xv[(size_t)MTOT * KVD];
__device__ float g_attn[(size_t)MTOT * DIM];
__device__ float g_xr[(size_t)MTOT * DIM];      // tf32-rounded x
__device__ float g_wqt[(size_t)DIM * DIM];      // transposed+rounded [N][K]
__device__ float g_wkt[(size_t)KVD * DIM];
__device__ float g_wvt[(size_t)KVD * DIM];
__device__ float g_wot[(size_t)DIM * DIM];

__device__ __forceinline__ float f2tf_f(float f) {
    unsigned u;
    asm("cvt.rna.tf32.f32 %0, %1;" : "=r"(u) : "f"(f));
    return __uint_as_float(u);
}

// ---------------- tf32 round pass (elementwise) ---------------------------
__global__ __launch_bounds__(256)
void round_kernel(const float4* __restrict__ src, float4* __restrict__ dst)
{
    const int i = blockIdx.x * 256 + threadIdx.x;
    float4 v = src[i];
    v.x = f2tf_f(v.x); v.y = f2tf_f(v.y); v.z = f2tf_f(v.z); v.w = f2tf_f(v.w);
    dst[i] = v;
}

// ---------------- transpose + tf32 round: w[K,N] -> wt[N][K] --------------
__global__ __launch_bounds__(256)
void transpose_round(const float* __restrict__ w, float* __restrict__ wt,
                     int K, int N)
{
    __shared__ float t[32][33];
    const int k0 = blockIdx.y * 32, n0 = blockIdx.x * 32;
    const int r = threadIdx.x >> 5, cc = threadIdx.x & 31;
#pragma unroll
    for (int i = 0; i < 4; i++)
        t[r + i * 8][cc] = w[(size_t)(k0 + r + i * 8) * N + n0 + cc];
    __syncthreads();
#pragma unroll
    for (int i = 0; i < 4; i++)
        wt[(size_t)(n0 + r + i * 8) * K + k0 + cc] = f2tf_f(t[cc][r + i * 8]);
}

// ================= tf32 tensor-core GEMM v3 (ldmatrix) ===================
// C[M,N] = A[M,K] @ Bt[N,K]^T, all fp32 pre-rounded to tf32.
// Block 128x256, 8 warps (2M x 4N), warp 64x64, BK=32, 3-stage cp.async.
// Both A and B smem tiles are K-major with 36-word pitch; fragments loaded
// with ldmatrix.x4 (b16 view of 32-bit data).
#define V3_BM 128
#define V3_BN 256
#define V3_BK 32
#define PITCH 36                                 // words per row (144 B)
#define A_WORDS (V3_BM * PITCH)                  // 4608
#define B_WORDS (V3_BN * PITCH)                  // 9216
#define STG_WORDS (A_WORDS + B_WORDS)            // 13824
#define V3_SMEM (3 * STG_WORDS * 4)              // 165888 B

__device__ __forceinline__ uint32_t smem_u32(const void* p) {
    uint32_t a;
    asm("{ .reg .u64 t; cvta.to.shared.u64 t, %1; cvt.u32.u64 %0, t; }"
        : "=r"(a) : "l"(p));
    return a;
}
__device__ __forceinline__ void cp16(uint32_t dst, const void* src) {
    asm volatile("cp.async.cg.shared.global [%0], [%1], 16;"
                 :: "r"(dst), "l"(src) : "memory");
}
#define CP_COMMIT() asm volatile("cp.async.commit_group;" ::: "memory")
#define CP_WAIT2()  asm volatile("cp.async.wait_group 2;" ::: "memory")

__device__ __forceinline__ void mma_tf32(float* d, uint32_t a0, uint32_t a1,
                                         uint32_t a2, uint32_t a3,
                                         uint32_t b0, uint32_t b1) {
    asm volatile(
        "mma.sync.aligned.m16n8k8.row.col.f32.tf32.tf32.f32 "
        "{%0,%1,%2,%3},{%4,%5,%6,%7},{%8,%9},{%0,%1,%2,%3};"
        : "+f"(d[0]), "+f"(d[1]), "+f"(d[2]), "+f"(d[3])
        : "r"(a0), "r"(a1), "r"(a2), "r"(a3), "r"(b0), "r"(b1));
}
__device__ __forceinline__ void ldm_x4(uint32_t& r0, uint32_t& r1,
                                       uint32_t& r2, uint32_t& r3, uint32_t a) {
    asm volatile("ldmatrix.sync.aligned.m8n8.x4.shared.b16 {%0,%1,%2,%3}, [%4];"
                 : "=r"(r0), "=r"(r1), "=r"(r2), "=r"(r3) : "r"(a));
}

__global__ __launch_bounds__(256, 1)
void tf32_gemm3(const float* __restrict__ A, const float* __restrict__ Bt,
                float* __restrict__ C, int M, int N, int K)
{
    extern __shared__ float smem[];
    const int tid  = threadIdx.x;
    const int wid  = tid >> 5;
    const int lane = tid & 31;
    const int warpM = wid >> 2;          // 0..1
    const int warpN = wid & 3;           // 0..3
    const int g = lane >> 2;
    const int c = lane & 3;

    const int bm = blockIdx.y * V3_BM;
    const int bn = blockIdx.x * V3_BN;
    const uint32_t sb = smem_u32(smem);

    float acc[4][8][4];
#pragma unroll
    for (int i = 0; i < 4; i++)
#pragma unroll
        for (int j = 0; j < 8; j++)
#pragma unroll
            for (int r = 0; r < 4; r++) acc[i][j][r] = 0.f;

    const int nt = K / V3_BK;

    // cp.async: A 128 rows x 8 f4-chunks, B 256 rows x 8 f4-chunks
    auto issue = [&](int t, int buf) {
        const uint32_t base = sb + buf * STG_WORDS * 4;
#pragma unroll
        for (int v = 0; v < 4; v++) {
            int lin = v * 256 + tid;
            int r = lin >> 3, c4 = (lin & 7) << 2;
            cp16(base + (r * PITCH + c4) * 4,
                 A + (size_t)(bm + r) * K + t * V3_BK + c4);
        }
        const uint32_t bbase = base + A_WORDS * 4;
#pragma unroll
        for (int v = 0; v < 8; v++) {
            int lin = v * 256 + tid;
            int r = lin >> 3, c4 = (lin & 7) << 2;
            cp16(bbase + (r * PITCH + c4) * 4,
                 Bt + (size_t)(bn + r) * K + t * V3_BK + c4);
        }
        CP_COMMIT();
    };

    issue(0, 0);
    issue(1, 1);

    // ldmatrix lane-address components (in words)
    const int a_row = ((lane >> 3) & 1) * 8 + (lane & 7);   // within 16-row m-tile
    const int a_kw  = (lane >> 4) * 4;                      // 0 or 4
    const int b_row = (lane >> 4) * 8 + (lane & 7);         // within 16-row n-tile
    const int b_kw  = ((lane >> 3) & 1) * 4;                // 0 or 4

    for (int t = 0; t < nt; t++) {
        if (t + 2 < nt) issue(t + 2, (t + 2) % 3);
        CP_WAIT2();
        __syncthreads();

        const uint32_t base  = sb + (t % 3) * STG_WORDS * 4;
        const uint32_t abase = base + ((warpM * 64 + a_row) * PITCH + a_kw) * 4;
        const uint32_t bbase = base + A_WORDS * 4 +
                               ((warpN * 64 + b_row) * PITCH + b_kw) * 4;

#pragma unroll
        for (int kk = 0; kk < 4; kk++) {
            const uint32_t kofs = kk * 8 * 4;       // 8 words per kk step
            uint32_t a[4][4], b[8][2];
#pragma unroll
            for (int mi = 0; mi < 4; mi++)
                ldm_x4(a[mi][0], a[mi][1], a[mi][2], a[mi][3],
                       abase + mi * 16 * PITCH * 4 + kofs);
#pragma unroll
            for (int ni = 0; ni < 4; ni++)
                ldm_x4(b[ni * 2][0], b[ni * 2][1], b[ni * 2 + 1][0], b[ni * 2 + 1][1],
                       bbase + ni * 16 * PITCH * 4 + kofs);
#pragma unroll
            for (int mi = 0; mi < 4; mi++)
#pragma unroll
                for (int j = 0; j < 8; j++)
                    mma_tf32(acc[mi][j], a[mi][0], a[mi][1], a[mi][2], a[mi][3],
                             b[j][0], b[j][1]);
        }
        __syncthreads();
    }

#pragma unroll
    for (int mi = 0; mi < 4; mi++) {
        int row = bm + warpM * 64 + mi * 16 + g;
#pragma unroll
        for (int j = 0; j < 8; j++) {
            int col = bn + warpN * 64 + j * 8 + 2 * c;
            float2 v0, v1;
            v0.x = acc[mi][j][0]; v0.y = acc[mi][j][1];
            v1.x = acc[mi][j][2]; v1.y = acc[mi][j][3];
            *(float2*)(C + (size_t)row * N + col)       = v0;
            *(float2*)(C + (size_t)(row + 8) * N + col) = v1;
        }
    }
}

// ---------------- RoPE (in place) ----------------------------------------
__global__ __launch_bounds__(256)
void rope_kernel(float2* __restrict__ x, const float* __restrict__ cs,
                 const float* __restrict__ sn, int heads)
{
    const int idx = blockIdx.x * blockDim.x + threadIdx.x;
    const int pair = idx & 63;
    const int row  = idx >> 6;
    const int s    = (row / heads) & (SEQ - 1);
    const float c  = cs[s * 64 + pair];
    const float si = sn[s * 64 + pair];
    float2 v = x[idx];
    float2 o;
    o.x = v.x * c - v.y * si;
    o.y = v.x * si + v.y * c;
    x[idx] = o;
}

// ============ bf16-split tensor-core flash attention =====================
#define QPITCH 136
#define KPITCH 136
#define VPITCH 68
#define OFF_QH 0
#define OFF_QL (OFF_QH + 128 * QPITCH * 2)
#define OFF_KH (OFF_QL + 128 * QPITCH * 2)
#define OFF_KL (OFF_KH + 64 * KPITCH * 2)
#define OFF_VH (OFF_KL + 64 * KPITCH * 2)
#define OFF_VL (OFF_VH + 128 * VPITCH * 2)
#define ATT_SMEM (OFF_VL + 128 * VPITCH * 2)     // 139264

__device__ __forceinline__ void mma_bf16(float* d, uint32_t a0, uint32_t a1,
                                         uint32_t a2, uint32_t a3,
                                         uint32_t b0, uint32_t b1) {
    asm volatile(
        "mma.sync.aligned.m16n8k16.row.col.f32.bf16.bf16.f32 "
        "{%0,%1,%2,%3},{%4,%5,%6,%7},{%8,%9},{%0,%1,%2,%3};"
        : "+f"(d[0]), "+f"(d[1]), "+f"(d[2]), "+f"(d[3])
        : "r"(a0), "r"(a1), "r"(a2), "r"(a3), "r"(b0), "r"(b1));
}
__device__ __forceinline__ uint32_t packbf(__nv_bfloat16 lo, __nv_bfloat16 hi) {
    __nv_bfloat162 p(lo, hi);
    return *(uint32_t*)&p;
}
__device__ __forceinline__ uint32_t pack_f2(float lo, float hi) {
    return packbf(__float2bfloat16_rn(lo), __float2bfloat16_rn(hi));
}
__device__ __forceinline__ void split2(float v, __nv_bfloat16& h, __nv_bfloat16& l) {
    h = __float2bfloat16_rn(v);
    l = __float2bfloat16_rn(v - __bfloat162float(h));
}
__device__ __forceinline__ uint32_t ld32s(const __nv_bfloat16* p) {
    return *(const uint32_t*)p;
}

__global__ __launch_bounds__(256, 1)
void attention_mma(const float* __restrict__ q, const float* __restrict__ k,
                   const float* __restrict__ v, float* __restrict__ o)
{
    extern __shared__ char sm[];
    __nv_bfloat16* Qh  = (__nv_bfloat16*)(sm + OFF_QH);
    __nv_bfloat16* Ql  = (__nv_bfloat16*)(sm + OFF_QL);
    __nv_bfloat16* Kh  = (__nv_bfloat16*)(sm + OFF_KH);
    __nv_bfloat16* Kl  = (__nv_bfloat16*)(sm + OFF_KL);
    __nv_bfloat16* Vth = (__nv_bfloat16*)(sm + OFF_VH);
    __nv_bfloat16* Vtl = (__nv_bfloat16*)(sm + OFF_VL);

    const int tid  = threadIdx.x;
    const int wid  = tid >> 5;
    const int lane = tid & 31;
    const int g = lane >> 2;
    const int c = lane & 3;
    const int b  = blockIdx.z;
    const int h  = blockIdx.y;
    const int kvh = h >> 2;
    const int q0 = blockIdx.x * 128;

    const float inv_sqrt = 0.08838834764831845f;

    {
        const float* qb = q + ((size_t)(b * SEQ + q0) * NH + h) * HD;
#pragma unroll
        for (int i = 0; i < 16; i++) {
            int lin = i * 256 + tid;
            int r = lin >> 5, d4 = (lin & 31) << 2;
            float4 qv = *(const float4*)(qb + (size_t)r * (NH * HD) + d4);
            qv.x *= inv_sqrt; qv.y *= inv_sqrt; qv.z *= inv_sqrt; qv.w *= inv_sqrt;
            __nv_bfloat16 h0, h1, h2, h3, l0, l1, l2, l3;
            split2(qv.x, h0, l0); split2(qv.y, h1, l1);
            split2(qv.z, h2, l2); split2(qv.w, h3, l3);
            uint2 hv, lv;
            hv.x = packbf(h0, h1); hv.y = packbf(h2, h3);
            lv.x = packbf(l0, l1); lv.y = packbf(l2, l3);
            *(uint2*)(Qh + r * QPITCH + d4) = hv;
            *(uint2*)(Ql + r * QPITCH + d4) = lv;
        }
    }

    float m0 = -1e30f, m1 = -1e30f, l0s = 0.f, l1s = 0.f;
    float oacc[16][4];
#pragma unroll
    for (int j = 0; j < 16; j++)
#pragma unroll
        for (int r = 0; r < 4; r++) oacc[j][r] = 0.f;

    const float* kb0 = k + ((size_t)(b * SEQ) * NKV + kvh) * HD;
    const float* vb0 = v + ((size_t)(b * SEQ) * NKV + kvh) * HD;

    for (int kt = 0; kt < SEQ / 64; kt++) {
        __syncthreads();
        {
            const float* kb = kb0 + (size_t)(kt * 64) * KVD;
#pragma unroll
            for (int i = 0; i < 8; i++) {
                int lin = i * 256 + tid;
                int r = lin >> 5, d4 = (lin & 31) << 2;
                float4 kv = *(const float4*)(kb + (size_t)r * KVD + d4);
                __nv_bfloat16 h0, h1, h2, h3, lo0, lo1, lo2, lo3;
                split2(kv.x, h0, lo0); split2(kv.y, h1, lo1);
                split2(kv.z, h2, lo2); split2(kv.w, h3, lo3);
                uint2 hv, lv;
                hv.x = packbf(h0, h1); hv.y = packbf(h2, h3);
                lv.x = packbf(lo0, lo1); lv.y = packbf(lo2, lo3);
                *(uint2*)(Kh + r * KPITCH + d4) = hv;
                *(uint2*)(Kl + r * KPITCH + d4) = lv;
            }
        }
        {
            const float* vb = vb0 + (size_t)(kt * 64) * KVD;
            const int d  = tid & 127;
            const int rg = (tid >> 7) << 2;
#pragma unroll
            for (int it = 0; it < 8; it++) {
                int r0 = rg + it * 8;
                __nv_bfloat16 vh[4], vl[4];
#pragma unroll
                for (int i = 0; i < 4; i++) {
                    float val = vb[(size_t)(r0 + i) * KVD + d];
                    split2(val, vh[i], vl[i]);
                }
                uint2 hv, lv;
                hv.x = packbf(vh[0], vh[1]); hv.y = packbf(vh[2], vh[3]);
                lv.x = packbf(vl[0], vl[1]); lv.y = packbf(vl[2], vl[3]);
                *(uint2*)(Vth + d * VPITCH + r0) = hv;
                *(uint2*)(Vtl + d * VPITCH + r0) = lv;
            }
        }
        __syncthreads();

        float s[8][4];
#pragma unroll
        for (int j = 0; j < 8; j++)
#pragma unroll
            for (int r = 0; r < 4; r++) s[j][r] = 0.f;

#pragma unroll
        for (int kk = 0; kk < 8; kk++) {
            const int dofs = kk * 16 + 2 * c;
            const __nv_bfloat16* qhp = Qh + (wid * 16 + g) * QPITCH + dofs;
            const __nv_bfloat16* qlp = Ql + (wid * 16 + g) * QPITCH + dofs;
            uint32_t ah0 = ld32s(qhp),     ah1 = ld32s(qhp + 8 * QPITCH);
            uint32_t ah2 = ld32s(qhp + 8), ah3 = ld32s(qhp + 8 * QPITCH + 8);
            uint32_t al0 = ld32s(qlp),     al1 = ld32s(qlp + 8 * QPITCH);
            uint32_t al2 = ld32s(qlp + 8), al3 = ld32s(qlp + 8 * QPITCH + 8);
#pragma unroll
            for (int j = 0; j < 8; j++) {
                const __nv_bfloat16* khp = Kh + (8 * j + g) * KPITCH + dofs;
                const __nv_bfloat16* klp = Kl + (8 * j + g) * KPITCH + dofs;
                uint32_t bh0 = ld32s(khp), bh1 = ld32s(khp + 8);
                uint32_t bl0 = ld32s(klp), bl1 = ld32s(klp + 8);
                mma_bf16(s[j], ah0, ah1, ah2, ah3, bh0, bh1);
                mma_bf16(s[j], ah0, ah1, ah2, ah3, bl0, bl1);
                mma_bf16(s[j], al0, al1, al2, al3, bh0, bh1);
            }
        }

        float mx0 = s[0][0], mx1 = s[0][2];
#pragma unroll
        for (int j = 0; j < 8; j++) {
            mx0 = fmaxf(mx0, fmaxf(s[j][0], s[j][1]));
            mx1 = fmaxf(mx1, fmaxf(s[j][2], s[j][3]));
        }
        mx0 = fmaxf(mx0, __shfl_xor_sync(0xffffffffu, mx0, 1));
        mx0 = fmaxf(mx0, __shfl_xor_sync(0xffffffffu, mx0, 2));
        mx1 = fmaxf(mx1, __shfl_xor_sync(0xffffffffu, mx1, 1));
        mx1 = fmaxf(mx1, __shfl_xor_sync(0xffffffffu, mx1, 2));
        float mn0 = fmaxf(m0, mx0), mn1 = fmaxf(m1, mx1);
        float f0 = __expf(m0 - mn0), f1 = __expf(m1 - mn1);
        float rs0 = 0.f, rs1 = 0.f;
#pragma unroll
        for (int j = 0; j < 8; j++) {
            s[j][0] = __expf(s[j][0] - mn0);
            s[j][1] = __expf(s[j][1] - mn0);
            s[j][2] = __expf(s[j][2] - mn1);
            s[j][3] = __expf(s[j][3] - mn1);
            rs0 += s[j][0] + s[j][1];
            rs1 += s[j][2] + s[j][3];
        }
        rs0 += __shfl_xor_sync(0xffffffffu, rs0, 1);
        rs0 += __shfl_xor_sync(0xffffffffu, rs0, 2);
        rs1 += __shfl_xor_sync(0xffffffffu, rs1, 1);
        rs1 += __shfl_xor_sync(0xffffffffu, rs1, 2);
        l0s = l0s * f0 + rs0;
        l1s = l1s * f1 + rs1;
        m0 = mn0; m1 = mn1;
#pragma unroll
        for (int j = 0; j < 16; j++) {
            oacc[j][0] *= f0; oacc[j][1] *= f0;
            oacc[j][2] *= f1; oacc[j][3] *= f1;
        }

#pragma unroll
        for (int kk = 0; kk < 4; kk++) {
            const int j0 = 2 * kk, j1 = 2 * kk + 1;
            uint32_t ph0 = pack_f2(s[j0][0], s[j0][1]);
            uint32_t ph1 = pack_f2(s[j0][2], s[j0][3]);
            uint32_t ph2 = pack_f2(s[j1][0], s[j1][1]);
            uint32_t ph3 = pack_f2(s[j1][2], s[j1][3]);
            __nv_bfloat162 h0 = *(__nv_bfloat162*)&ph0;
            __nv_bfloat162 h1 = *(__nv_bfloat162*)&ph1;
            __nv_bfloat162 h2 = *(__nv_bfloat162*)&ph2;
            __nv_bfloat162 h3 = *(__nv_bfloat162*)&ph3;
            uint32_t pl0 = pack_f2(s[j0][0] - __bfloat162float(h0.x),
                                   s[j0][1] - __bfloat162float(h0.y));
            uint32_t pl1 = pack_f2(s[j0][2] - __bfloat162float(h1.x),
                                   s[j0][3] - __bfloat162float(h1.y));
            uint32_t pl2 = pack_f2(s[j1][0] - __bfloat162float(h2.x),
                                   s[j1][1] - __bfloat162float(h2.y));
            uint32_t pl3 = pack_f2(s[j1][2] - __bfloat162float(h3.x),
                                   s[j1][3] - __bfloat162float(h3.y));
            const int kofs = kk * 16 + 2 * c;
#pragma unroll
            for (int j = 0; j < 16; j++) {
                const __nv_bfloat16* vhp = Vth + (8 * j + g) * VPITCH + kofs;
                const __nv_bfloat16* vlp = Vtl + (8 * j + g) * VPITCH + kofs;
                uint32_t bh0 = ld32s(vhp), bh1 = ld32s(vhp + 8);
                uint32_t bl0 = ld32s(vlp), bl1 = ld32s(vlp + 8);
                mma_bf16(oacc[j], ph0, ph1, ph2, ph3, bh0, bh1);
                mma_bf16(oacc[j], ph0, ph1, ph2, ph3, bl0, bl1);
                mma_bf16(oacc[j], pl0, pl1, pl2, pl3, bh0, bh1);
            }
        }
    }

    // normalize + write tf32-rounded (feeds the final GEMM's A side)
    const float inv0 = 1.f / l0s, inv1 = 1.f / l1s;
    float* ob  = o + ((size_t)(b * SEQ + q0 + wid * 16 + g) * NH + h) * HD;
    float* ob8 = ob + (size_t)8 * NH * HD;
#pragma unroll
    for (int j = 0; j < 16; j++) {
        int col = j * 8 + 2 * c;
        float2 v0, v1;
        v0.x = f2tf_f(oacc[j][0] * inv0); v0.y = f2tf_f(oacc[j][1] * inv0);
        v1.x = f2tf_f(oacc[j][2] * inv1); v1.y = f2tf_f(oacc[j][3] * inv1);
        *(float2*)(ob + col)  = v0;
        *(float2*)(ob8 + col) = v1;
    }
}

// ---------------- launch -------------------------------------------------
extern "C" void kernel_launch(void* const* d_in, const int* in_sizes, int n_in,
                              void* d_out, int out_size)
{
    (void)in_sizes; (void)n_in; (void)out_size;
    const float* x  = (const float*)d_in[0];
    const float* wq = (const float*)d_in[1];
    const float* wk = (const float*)d_in[2];
    const float* wv = (const float*)d_in[3];
    const float* wo = (const float*)d_in[4];
    const float* fc = (const float*)d_in[5];
    const float* fs = (const float*)d_in[6];
    float* out = (float*)d_out;

    float *xq, *xk, *xv, *attn, *xr, *wqt, *wkt, *wvt, *wot;
    cudaGetSymbolAddress((void**)&xq,   g_xq);
    cudaGetSymbolAddress((void**)&xk,   g_xk);
    cudaGetSymbolAddress((void**)&xv,   g_xv);
    cudaGetSymbolAddress((void**)&attn, g_attn);
    cudaGetSymbolAddress((void**)&xr,   g_xr);
    cudaGetSymbolAddress((void**)&wqt,  g_wqt);
    cudaGetSymbolAddress((void**)&wkt,  g_wkt);
    cudaGetSymbolAddress((void**)&wvt,  g_wvt);
    cudaGetSymbolAddress((void**)&wot,  g_wot);

    cudaFuncSetAttribute(tf32_gemm3,
                         cudaFuncAttributeMaxDynamicSharedMemorySize, V3_SMEM);
    cudaFuncSetAttribute(attention_mma,
                         cudaFuncAttributeMaxDynamicSharedMemorySize, ATT_SMEM);

    // pre-processing: round x, transpose+round weights to [N][K]
    round_kernel<<<(MTOT * DIM / 4) / 256, 256>>>((const float4*)x, (float4*)xr);
    transpose_round<<<dim3(DIM / 32, DIM / 32), 256>>>(wq, wqt, DIM, DIM);
    transpose_round<<<dim3(KVD / 32, DIM / 32), 256>>>(wk, wkt, DIM, KVD);
    transpose_round<<<dim3(KVD / 32, DIM / 32), 256>>>(wv, wvt, DIM, KVD);
    transpose_round<<<dim3(DIM / 32, DIM / 32), 256>>>(wo, wot, DIM, DIM);

    // QKV projections
    tf32_gemm3<<<dim3(DIM / V3_BN, MTOT / V3_BM), 256, V3_SMEM>>>(xr, wqt, xq, MTOT, DIM, DIM);
    tf32_gemm3<<<dim3(KVD / V3_BN, MTOT / V3_BM), 256, V3_SMEM>>>(xr, wkt, xk, MTOT, KVD, DIM);
    tf32_gemm3<<<dim3(KVD / V3_BN, MTOT / V3_BM), 256, V3_SMEM>>>(xr, wvt, xv, MTOT, KVD, DIM);

    // RoPE
    rope_kernel<<<(MTOT * NH * (HD / 2)) / 256, 256>>>((float2*)xq, fc, fs, NH);
    rope_kernel<<<(MTOT * NKV * (HD / 2)) / 256, 256>>>((float2*)xk, fc, fs, NKV);

    // attention (bf16-split mma)
    attention_mma<<<dim3(SEQ / 128, NH, BATCH), 256, ATT_SMEM>>>(xq, xk, xv, attn);

    // output projection (attn already tf32-rounded by attention epilogue)
    tf32_gemm3<<<dim3(DIM / V3_BN, MTOT / V3_BM), 256, V3_SMEM>>>(attn, wot, out, MTOT, DIM, DIM);
}

// round 7
// speedup vs baseline: 1.9503x; 1.3715x over previous
#include <cuda_runtime.h>
#include <cuda_bf16.h>
#include <cuda_fp16.h>
#include <cstdint>

// Problem dims (fixed)
#define BATCH 2
#define SEQ   2048
#define DIM   4096
#define NH    32
#define NKV   8
#define HD    128
#define MTOT  (BATCH*SEQ)          // 4096
#define KVD   (NKV*HD)             // 1024
#define QKVN  (DIM + 2*KVD)        // 6144 fused N
#define QOFF  0
#define KOFF  DIM                  // 4096
#define VOFF  (DIM + KVD)          // 5120

// ---------------- scratch (static device globals; no allocation) ----------
__device__ __half g_xh[(size_t)MTOT * DIM];          // fp16 x
__device__ __half g_wcat[(size_t)QKVN * DIM];        // [6144][4096] wq|wk|wv ^T
__device__ __half g_wot[(size_t)DIM * DIM];          // woT [N][K]
__device__ float  g_qkv[(size_t)MTOT * QKVN];        // fused qkv output
__device__ __half g_ah[(size_t)MTOT * DIM];          // attention out fp16

// ---------------- helpers -------------------------------------------------
__device__ __forceinline__ uint32_t smem_u32(const void* p) {
    uint32_t a;
    asm("{ .reg .u64 t; cvta.to.shared.u64 t, %1; cvt.u32.u64 %0, t; }"
        : "=r"(a) : "l"(p));
    return a;
}
__device__ __forceinline__ void cp16(uint32_t dst, const void* src) {
    asm volatile("cp.async.cg.shared.global [%0], [%1], 16;"
                 :: "r"(dst), "l"(src) : "memory");
}
#define CP_COMMIT() asm volatile("cp.async.commit_group;" ::: "memory")
#define CP_WAIT2()  asm volatile("cp.async.wait_group 2;" ::: "memory")

__device__ __forceinline__ void mma_f16(float* d, uint32_t a0, uint32_t a1,
                                        uint32_t a2, uint32_t a3,
                                        uint32_t b0, uint32_t b1) {
    asm volatile(
        "mma.sync.aligned.m16n8k16.row.col.f32.f16.f16.f32 "
        "{%0,%1,%2,%3},{%4,%5,%6,%7},{%8,%9},{%0,%1,%2,%3};"
        : "+f"(d[0]), "+f"(d[1]), "+f"(d[2]), "+f"(d[3])
        : "r"(a0), "r"(a1), "r"(a2), "r"(a3), "r"(b0), "r"(b1));
}
__device__ __forceinline__ void mma_bf16(float* d, uint32_t a0, uint32_t a1,
                                         uint32_t a2, uint32_t a3,
                                         uint32_t b0, uint32_t b1) {
    asm volatile(
        "mma.sync.aligned.m16n8k16.row.col.f32.bf16.bf16.f32 "
        "{%0,%1,%2,%3},{%4,%5,%6,%7},{%8,%9},{%0,%1,%2,%3};"
        : "+f"(d[0]), "+f"(d[1]), "+f"(d[2]), "+f"(d[3])
        : "r"(a0), "r"(a1), "r"(a2), "r"(a3), "r"(b0), "r"(b1));
}
__device__ __forceinline__ void ldm_x4(uint32_t& r0, uint32_t& r1,
                                       uint32_t& r2, uint32_t& r3, uint32_t a) {
    asm volatile("ldmatrix.sync.aligned.m8n8.x4.shared.b16 {%0,%1,%2,%3}, [%4];"
                 : "=r"(r0), "=r"(r1), "=r"(r2), "=r"(r3) : "r"(a));
}
__device__ __forceinline__ uint32_t packbf(__nv_bfloat16 lo, __nv_bfloat16 hi) {
    __nv_bfloat162 p(lo, hi);
    return *(uint32_t*)&p;
}
__device__ __forceinline__ uint32_t pack_f2(float lo, float hi) {
    return packbf(__float2bfloat16_rn(lo), __float2bfloat16_rn(hi));
}
__device__ __forceinline__ void split2(float v, __nv_bfloat16& h, __nv_bfloat16& l) {
    h = __float2bfloat16_rn(v);
    l = __float2bfloat16_rn(v - __bfloat162float(h));
}
__device__ __forceinline__ uint32_t ld32s(const __nv_bfloat16* p) {
    return *(const uint32_t*)p;
}

// ================= fp16 tensor-core GEMM (ldmatrix, k16) =================
// C[M,N] = A[M,K]fp16 @ Bt[N,K]fp16^T, fp32 out. Block 128x256, 8 warps
// (2M x 4N), warp 64x64, BK=64 halves, 3-stage cp.async.
#define HG_BM 128
#define HG_BN 256
#define HG_BK 64
#define HPITCH 72                                // halves per row (144 B)
#define A_HALVES (HG_BM * HPITCH)                // 9216
#define B_HALVES (HG_BN * HPITCH)                // 18432
#define STG_HALVES (A_HALVES + B_HALVES)         // 27648
#define HG_SMEM (3 * STG_HALVES * 2)             // 165888 B

__global__ __launch_bounds__(256, 1)
void hgemm(const __half* __restrict__ A, const __half* __restrict__ Bt,
           float* __restrict__ C, int M, int N, int K)
{
    extern __shared__ char smemc[];
    const uint32_t sb = smem_u32(smemc);
    const int tid  = threadIdx.x;
    const int wid  = tid >> 5;
    const int lane = tid & 31;
    const int warpM = wid >> 2;          // 0..1
    const int warpN = wid & 3;           // 0..3
    const int g = lane >> 2;
    const int c = lane & 3;

    const int bm = blockIdx.y * HG_BM;
    const int bn = blockIdx.x * HG_BN;

    float acc[4][8][4];
#pragma unroll
    for (int i = 0; i < 4; i++)
#pragma unroll
        for (int j = 0; j < 8; j++)
#pragma unroll
            for (int r = 0; r < 4; r++) acc[i][j][r] = 0.f;

    const int nt = K / HG_BK;

    // cp.async: A 128 rows x 8 16B-chunks (1024) -> 4/thr; B 256 rows -> 8/thr
    auto issue = [&](int t, int buf) {
        const uint32_t base = sb + buf * STG_HALVES * 2;
#pragma unroll
        for (int v = 0; v < 4; v++) {
            int lin = v * 256 + tid;
            int r = lin >> 3, c8 = (lin & 7) << 3;
            cp16(base + (r * HPITCH + c8) * 2,
                 A + (size_t)(bm + r) * K + t * HG_BK + c8);
        }
        const uint32_t bbase = base + A_HALVES * 2;
#pragma unroll
        for (int v = 0; v < 8; v++) {
            int lin = v * 256 + tid;
            int r = lin >> 3, c8 = (lin & 7) << 3;
            cp16(bbase + (r * HPITCH + c8) * 2,
                 Bt + (size_t)(bn + r) * K + t * HG_BK + c8);
        }
        CP_COMMIT();
    };

    issue(0, 0);
    issue(1, 1);

    const int lrow = lane & 15;
    const int lcol = (lane >> 4) * 8;     // halves

    for (int t = 0; t < nt; t++) {
        if (t + 2 < nt) issue(t + 2, (t + 2) % 3);
        CP_WAIT2();
        __syncthreads();

        const uint32_t base  = sb + (t % 3) * STG_HALVES * 2;
        const uint32_t abase = base + ((warpM * 64 + lrow) * HPITCH + lcol) * 2;
        const uint32_t bbase = base + A_HALVES * 2 +
                               ((warpN * 64 + lrow) * HPITCH + lcol) * 2;

#pragma unroll
        for (int kk = 0; kk < 4; kk++) {        // 4 k16 steps in BK=64
            const uint32_t kofs = kk * 16 * 2;
            uint32_t a[4][4], b[8][2];
#pragma unroll
            for (int mi = 0; mi < 4; mi++)
                ldm_x4(a[mi][0], a[mi][1], a[mi][2], a[mi][3],
                       abase + mi * 16 * HPITCH * 2 + kofs);
#pragma unroll
            for (int ni = 0; ni < 4; ni++) {
                uint32_t r0, r1, r2, r3;
                ldm_x4(r0, r1, r2, r3, bbase + ni * 16 * HPITCH * 2 + kofs);
                b[ni * 2][0] = r0; b[ni * 2][1] = r2;
                b[ni * 2 + 1][0] = r1; b[ni * 2 + 1][1] = r3;
            }
#pragma unroll
            for (int mi = 0; mi < 4; mi++)
#pragma unroll
                for (int j = 0; j < 8; j++)
                    mma_f16(acc[mi][j], a[mi][0], a[mi][1], a[mi][2], a[mi][3],
                            b[j][0], b[j][1]);
        }
        __syncthreads();
    }

#pragma unroll
    for (int mi = 0; mi < 4; mi++) {
        int row = bm + warpM * 64 + mi * 16 + g;
#pragma unroll
        for (int j = 0; j < 8; j++) {
            int col = bn + warpN * 64 + j * 8 + 2 * c;
            float2 v0, v1;
            v0.x = acc[mi][j][0]; v0.y = acc[mi][j][1];
            v1.x = acc[mi][j][2]; v1.y = acc[mi][j][3];
            *(float2*)(C + (size_t)row * N + col)       = v0;
            *(float2*)(C + (size_t)(row + 8) * N + col) = v1;
        }
    }
}

// ============ conversion kernels =========================================
__global__ __launch_bounds__(256)
void cvt_half(const float4* __restrict__ src, __half* __restrict__ dst)
{
    const int i = blockIdx.x * 256 + threadIdx.x;
    float4 v = src[i];
    __half2* p = (__half2*)(dst + (size_t)i * 4);
    p[0] = __floats2half2_rn(v.x, v.y);
    p[1] = __floats2half2_rn(v.z, v.w);
}

// transpose + fp16: w[K,N] fp32 -> wt[N][K] fp16 (wt already offset by caller)
__global__ __launch_bounds__(256)
void transpose_half(const float* __restrict__ w, __half* __restrict__ wt,
                    int K, int N)
{
    __shared__ float t[32][33];
    const int k0 = blockIdx.y * 32, n0 = blockIdx.x * 32;
    const int r = threadIdx.x >> 5, cc = threadIdx.x & 31;
#pragma unroll
    for (int i = 0; i < 4; i++)
        t[r + i * 8][cc] = w[(size_t)(k0 + r + i * 8) * N + n0 + cc];
    __syncthreads();
#pragma unroll
    for (int i = 0; i < 4; i++)
        wt[(size_t)(n0 + r + i * 8) * K + k0 + cc] = __float2half_rn(t[cc][r + i * 8]);
}

// ---------------- RoPE (in place on fused qkv, strided) -------------------
// base points at head-0 column of the q (or k) section.
__global__ __launch_bounds__(256)
void rope_kernel(float* __restrict__ base, const float* __restrict__ cs,
                 const float* __restrict__ sn, int hmask, int hshift)
{
    const int idx = blockIdx.x * 256 + threadIdx.x;
    const int pair  = idx & 63;
    const int rest  = idx >> 6;
    const int h     = rest & hmask;
    const int token = rest >> hshift;
    const int s     = token & (SEQ - 1);
    const float co  = cs[s * 64 + pair];
    const float si  = sn[s * 64 + pair];
    float2* p = (float2*)(base + (size_t)token * QKVN + h * HD) + pair;
    float2 v = *p;
    float2 o;
    o.x = v.x * co - v.y * si;
    o.y = v.x * si + v.y * co;
    *p = o;
}

// ============ bf16-split tensor-core flash attention =====================
// reads fused qkv (fp32, row stride QKVN), writes fp16 [M][4096]
#define QPITCH 136
#define KPITCH 136
#define VPITCH 68
#define OFF_QH 0
#define OFF_QL (OFF_QH + 128 * QPITCH * 2)
#define OFF_KH (OFF_QL + 128 * QPITCH * 2)
#define OFF_KL (OFF_KH + 64 * KPITCH * 2)
#define OFF_VH (OFF_KL + 64 * KPITCH * 2)
#define OFF_VL (OFF_VH + 128 * VPITCH * 2)
#define ATT_SMEM (OFF_VL + 128 * VPITCH * 2)     // 139264

__global__ __launch_bounds__(256, 1)
void attention_mma(const float* __restrict__ qkv, __half* __restrict__ o)
{
    extern __shared__ char sm[];
    __nv_bfloat16* Qh  = (__nv_bfloat16*)(sm + OFF_QH);
    __nv_bfloat16* Ql  = (__nv_bfloat16*)(sm + OFF_QL);
    __nv_bfloat16* Kh  = (__nv_bfloat16*)(sm + OFF_KH);
    __nv_bfloat16* Kl  = (__nv_bfloat16*)(sm + OFF_KL);
    __nv_bfloat16* Vth = (__nv_bfloat16*)(sm + OFF_VH);
    __nv_bfloat16* Vtl = (__nv_bfloat16*)(sm + OFF_VL);

    const int tid  = threadIdx.x;
    const int wid  = tid >> 5;
    const int lane = tid & 31;
    const int g = lane >> 2;
    const int c = lane & 3;
    const int b  = blockIdx.z;
    const int h  = blockIdx.y;
    const int kvh = h >> 2;
    const int q0 = blockIdx.x * 128;

    const float inv_sqrt = 0.08838834764831845f;

    {
        const float* qb = qkv + (size_t)(b * SEQ + q0) * QKVN + QOFF + h * HD;
#pragma unroll
        for (int i = 0; i < 16; i++) {
            int lin = i * 256 + tid;
            int r = lin >> 5, d4 = (lin & 31) << 2;
            float4 qv = *(const float4*)(qb + (size_t)r * QKVN + d4);
            qv.x *= inv_sqrt; qv.y *= inv_sqrt; qv.z *= inv_sqrt; qv.w *= inv_sqrt;
            __nv_bfloat16 h0, h1, h2, h3, l0, l1, l2, l3;
            split2(qv.x, h0, l0); split2(qv.y, h1, l1);
            split2(qv.z, h2, l2); split2(qv.w, h3, l3);
            uint2 hv, lv;
            hv.x = packbf(h0, h1); hv.y = packbf(h2, h3);
            lv.x = packbf(l0, l1); lv.y = packbf(l2, l3);
            *(uint2*)(Qh + r * QPITCH + d4) = hv;
            *(uint2*)(Ql + r * QPITCH + d4) = lv;
        }
    }

    float m0 = -1e30f, m1 = -1e30f, l0s = 0.f, l1s = 0.f;
    float oacc[16][4];
#pragma unroll
    for (int j = 0; j < 16; j++)
#pragma unroll
        for (int r = 0; r < 4; r++) oacc[j][r] = 0.f;

    const float* kb0 = qkv + (size_t)(b * SEQ) * QKVN + KOFF + kvh * HD;
    const float* vb0 = qkv + (size_t)(b * SEQ) * QKVN + VOFF + kvh * HD;

    for (int kt = 0; kt < SEQ / 64; kt++) {
        __syncthreads();
        {
            const float* kb = kb0 + (size_t)(kt * 64) * QKVN;
#pragma unroll
            for (int i = 0; i < 8; i++) {
                int lin = i * 256 + tid;
                int r = lin >> 5, d4 = (lin & 31) << 2;
                float4 kv = *(const float4*)(kb + (size_t)r * QKVN + d4);
                __nv_bfloat16 h0, h1, h2, h3, lo0, lo1, lo2, lo3;
                split2(kv.x, h0, lo0); split2(kv.y, h1, lo1);
                split2(kv.z, h2, lo2); split2(kv.w, h3, lo3);
                uint2 hv, lv;
                hv.x = packbf(h0, h1); hv.y = packbf(h2, h3);
                lv.x = packbf(lo0, lo1); lv.y = packbf(lo2, lo3);
                *(uint2*)(Kh + r * KPITCH + d4) = hv;
                *(uint2*)(Kl + r * KPITCH + d4) = lv;
            }
        }
        {
            const float* vb = vb0 + (size_t)(kt * 64) * QKVN;
            const int d  = tid & 127;
            const int rg = (tid >> 7) << 2;
#pragma unroll
            for (int it = 0; it < 8; it++) {
                int r0 = rg + it * 8;
                __nv_bfloat16 vh[4], vl[4];
#pragma unroll
                for (int i = 0; i < 4; i++) {
                    float val = vb[(size_t)(r0 + i) * QKVN + d];
                    split2(val, vh[i], vl[i]);
                }
                uint2 hv, lv;
                hv.x = packbf(vh[0], vh[1]); hv.y = packbf(vh[2], vh[3]);
                lv.x = packbf(vl[0], vl[1]); lv.y = packbf(vl[2], vl[3]);
                *(uint2*)(Vth + d * VPITCH + r0) = hv;
                *(uint2*)(Vtl + d * VPITCH + r0) = lv;
            }
        }
        __syncthreads();

        float s[8][4];
#pragma unroll
        for (int j = 0; j < 8; j++)
#pragma unroll
            for (int r = 0; r < 4; r++) s[j][r] = 0.f;

#pragma unroll
        for (int kk = 0; kk < 8; kk++) {
            const int dofs = kk * 16 + 2 * c;
            const __nv_bfloat16* qhp = Qh + (wid * 16 + g) * QPITCH + dofs;
            const __nv_bfloat16* qlp = Ql + (wid * 16 + g) * QPITCH + dofs;
            uint32_t ah0 = ld32s(qhp),     ah1 = ld32s(qhp + 8 * QPITCH);
            uint32_t ah2 = ld32s(qhp + 8), ah3 = ld32s(qhp + 8 * QPITCH + 8);
            uint32_t al0 = ld32s(qlp),     al1 = ld32s(qlp + 8 * QPITCH);
            uint32_t al2 = ld32s(qlp + 8), al3 = ld32s(qlp + 8 * QPITCH + 8);
#pragma unroll
            for (int j = 0; j < 8; j++) {
                const __nv_bfloat16* khp = Kh + (8 * j + g) * KPITCH + dofs;
                const __nv_bfloat16* klp = Kl + (8 * j + g) * KPITCH + dofs;
                uint32_t bh0 = ld32s(khp), bh1 = ld32s(khp + 8);
                uint32_t bl0 = ld32s(klp), bl1 = ld32s(klp + 8);
                mma_bf16(s[j], ah0, ah1, ah2, ah3, bh0, bh1);
                mma_bf16(s[j], ah0, ah1, ah2, ah3, bl0, bl1);
                mma_bf16(s[j], al0, al1, al2, al3, bh0, bh1);
            }
        }

        float mx0 = s[0][0], mx1 = s[0][2];
#pragma unroll
        for (int j = 0; j < 8; j++) {
            mx0 = fmaxf(mx0, fmaxf(s[j][0], s[j][1]));
            mx1 = fmaxf(mx1, fmaxf(s[j][2], s[j][3]));
        }
        mx0 = fmaxf(mx0, __shfl_xor_sync(0xffffffffu, mx0, 1));
        mx0 = fmaxf(mx0, __shfl_xor_sync(0xffffffffu, mx0, 2));
        mx1 = fmaxf(mx1, __shfl_xor_sync(0xffffffffu, mx1, 1));
        mx1 = fmaxf(mx1, __shfl_xor_sync(0xffffffffu, mx1, 2));
        float mn0 = fmaxf(m0, mx0), mn1 = fmaxf(m1, mx1);
        float f0 = __expf(m0 - mn0), f1 = __expf(m1 - mn1);
        float rs0 = 0.f, rs1 = 0.f;
#pragma unroll
        for (int j = 0; j < 8; j++) {
            s[j][0] = __expf(s[j][0] - mn0);
            s[j][1] = __expf(s[j][1] - mn0);
            s[j][2] = __expf(s[j][2] - mn1);
            s[j][3] = __expf(s[j][3] - mn1);
            rs0 += s[j][0] + s[j][1];
            rs1 += s[j][2] + s[j][3];
        }
        rs0 += __shfl_xor_sync(0xffffffffu, rs0, 1);
        rs0 += __shfl_xor_sync(0xffffffffu, rs0, 2);
        rs1 += __shfl_xor_sync(0xffffffffu, rs1, 1);
        rs1 += __shfl_xor_sync(0xffffffffu, rs1, 2);
        l0s = l0s * f0 + rs0;
        l1s = l1s * f1 + rs1;
        m0 = mn0; m1 = mn1;
#pragma unroll
        for (int j = 0; j < 16; j++) {
            oacc[j][0] *= f0; oacc[j][1] *= f0;
            oacc[j][2] *= f1; oacc[j][3] *= f1;
        }

#pragma unroll
        for (int kk = 0; kk < 4; kk++) {
            const int j0 = 2 * kk, j1 = 2 * kk + 1;
            uint32_t ph0 = pack_f2(s[j0][0], s[j0][1]);
            uint32_t ph1 = pack_f2(s[j0][2], s[j0][3]);
            uint32_t ph2 = pack_f2(s[j1][0], s[j1][1]);
            uint32_t ph3 = pack_f2(s[j1][2], s[j1][3]);
            __nv_bfloat162 h0 = *(__nv_bfloat162*)&ph0;
            __nv_bfloat162 h1 = *(__nv_bfloat162*)&ph1;
            __nv_bfloat162 h2 = *(__nv_bfloat162*)&ph2;
            __nv_bfloat162 h3 = *(__nv_bfloat162*)&ph3;
            uint32_t pl0 = pack_f2(s[j0][0] - __bfloat162float(h0.x),
                                   s[j0][1] - __bfloat162float(h0.y));
            uint32_t pl1 = pack_f2(s[j0][2] - __bfloat162float(h1.x),
                                   s[j0][3] - __bfloat162float(h1.y));
            uint32_t pl2 = pack_f2(s[j1][0] - __bfloat162float(h2.x),
                                   s[j1][1] - __bfloat162float(h2.y));
            uint32_t pl3 = pack_f2(s[j1][2] - __bfloat162float(h3.x),
                                   s[j1][3] - __bfloat162float(h3.y));
            const int kofs = kk * 16 + 2 * c;
#pragma unroll
            for (int j = 0; j < 16; j++) {
                const __nv_bfloat16* vhp = Vth + (8 * j + g) * VPITCH + kofs;
                const __nv_bfloat16* vlp = Vtl + (8 * j + g) * VPITCH + kofs;
                uint32_t bh0 = ld32s(vhp), bh1 = ld32s(vhp + 8);
                uint32_t bl0 = ld32s(vlp), bl1 = ld32s(vlp + 8);
                mma_bf16(oacc[j], ph0, ph1, ph2, ph3, bh0, bh1);
                mma_bf16(oacc[j], ph0, ph1, ph2, ph3, bl0, bl1);
                mma_bf16(oacc[j], pl0, pl1, pl2, pl3, bh0, bh1);
            }
        }
    }

    // normalize + write fp16 (A operand of the final GEMM)
    const float inv0 = 1.f / l0s, inv1 = 1.f / l1s;
    __half* ob  = o + (size_t)(b * SEQ + q0 + wid * 16 + g) * DIM + h * HD;
    __half* ob8 = ob + (size_t)8 * DIM;
#pragma unroll
    for (int j = 0; j < 16; j++) {
        int col = j * 8 + 2 * c;
        *(__half2*)(ob + col)  = __floats2half2_rn(oacc[j][0] * inv0, oacc[j][1] * inv0);
        *(__half2*)(ob8 + col) = __floats2half2_rn(oacc[j][2] * inv1, oacc[j][3] * inv1);
    }
}

// ---------------- launch -------------------------------------------------
extern "C" void kernel_launch(void* const* d_in, const int* in_sizes, int n_in,
                              void* d_out, int out_size)
{
    (void)in_sizes; (void)n_in; (void)out_size;
    const float* x  = (const float*)d_in[0];
    const float* wq = (const float*)d_in[1];
    const float* wk = (const float*)d_in[2];
    const float* wv = (const float*)d_in[3];
    const float* wo = (const float*)d_in[4];
    const float* fc = (const float*)d_in[5];
    const float* fs = (const float*)d_in[6];
    float* out = (float*)d_out;

    __half *xh, *wcat, *wot, *ah;
    float *qkv;
    cudaGetSymbolAddress((void**)&xh,   g_xh);
    cudaGetSymbolAddress((void**)&wcat, g_wcat);
    cudaGetSymbolAddress((void**)&wot,  g_wot);
    cudaGetSymbolAddress((void**)&qkv,  g_qkv);
    cudaGetSymbolAddress((void**)&ah,   g_ah);

    cudaFuncSetAttribute(hgemm,
                         cudaFuncAttributeMaxDynamicSharedMemorySize, HG_SMEM);
    cudaFuncSetAttribute(attention_mma,
                         cudaFuncAttributeMaxDynamicSharedMemorySize, ATT_SMEM);

    // conversions: x -> fp16; weights -> transposed fp16 (wq|wk|wv concat)
    cvt_half<<<(MTOT * DIM / 4) / 256, 256>>>((const float4*)x, xh);
    transpose_half<<<dim3(DIM / 32, DIM / 32), 256>>>(wq, wcat, DIM, DIM);
    transpose_half<<<dim3(KVD / 32, DIM / 32), 256>>>(wk, wcat + (size_t)KOFF * DIM, DIM, KVD);
    transpose_half<<<dim3(KVD / 32, DIM / 32), 256>>>(wv, wcat + (size_t)VOFF * DIM, DIM, KVD);
    transpose_half<<<dim3(DIM / 32, DIM / 32), 256>>>(wo, wot, DIM, DIM);

    // fused QKV projection: [4096][6144]
    hgemm<<<dim3(QKVN / HG_BN, MTOT / HG_BM), 256, HG_SMEM>>>(xh, wcat, qkv, MTOT, QKVN, DIM);

    // RoPE on q (32 heads) and k (8 heads) sections of qkv
    rope_kernel<<<(MTOT * NH * 64) / 256, 256>>>(qkv + QOFF, fc, fs, NH - 1, 5);
    rope_kernel<<<(MTOT * NKV * 64) / 256, 256>>>(qkv + KOFF, fc, fs, NKV - 1, 3);

    // attention (bf16-split mma), writes fp16
    attention_mma<<<dim3(SEQ / 128, NH, BATCH), 256, ATT_SMEM>>>(qkv, ah);

    // output projection
    hgemm<<<dim3(DIM / HG_BN, MTOT / HG_BM), 256, HG_SMEM>>>(ah, wot, out, MTOT, DIM, DIM);
}